// round 1
// baseline (speedup 1.0000x reference)
#include <cuda_runtime.h>

#define NX 1024
#define PLANE (NX * NX)
#define NB 16
#define TS 32            // output tile
#define EX 34            // extended tile (1-halo): advection stage
#define TH 36            // T tile (2-halo)
#define RED_BLOCKS 1024

__device__ float g_blockmax[RED_BLOCKS];
__device__ float g_dt;

// ---------------------------------------------------------------------------
// Pass 1: max(|u|,|v|) over channels 0,1 of all 16 batches.
// Element space: 16 chunks of 2*PLANE contiguous floats (2^21 each) -> 2^25 total.
// float4 grid-stride, per-block partial max (deterministic, no reset needed).
// ---------------------------------------------------------------------------
__global__ __launch_bounds__(256) void reduce_max_kernel(const float* __restrict__ in) {
    const unsigned total4 = (NB * 2u * PLANE) / 4u;   // 2^23
    float m = 0.f;
    for (unsigned i = blockIdx.x * blockDim.x + threadIdx.x; i < total4;
         i += gridDim.x * blockDim.x) {
        unsigned e   = i << 2;                        // element index in 2^25 space
        unsigned b   = e >> 21;                       // batch
        unsigned off = e & ((1u << 21) - 1u);         // offset within u+v planes
        const float4 v = *reinterpret_cast<const float4*>(in + (size_t)b * 4 * PLANE + off);
        m = fmaxf(m, fmaxf(fmaxf(fabsf(v.x), fabsf(v.y)),
                           fmaxf(fabsf(v.z), fabsf(v.w))));
    }
    #pragma unroll
    for (int o = 16; o; o >>= 1) m = fmaxf(m, __shfl_xor_sync(0xffffffffu, m, o));
    __shared__ float sm[8];
    if ((threadIdx.x & 31) == 0) sm[threadIdx.x >> 5] = m;
    __syncthreads();
    if (threadIdx.x < 32) {
        m = (threadIdx.x < 8) ? sm[threadIdx.x] : 0.f;
        #pragma unroll
        for (int o = 4; o; o >>= 1) m = fmaxf(m, __shfl_xor_sync(0xffffffffu, m, o));
        if (threadIdx.x == 0) g_blockmax[blockIdx.x] = m;
    }
}

// ---------------------------------------------------------------------------
// Pass 2: finalize dt from the 1024 partials; store to g_dt and d_out tail.
// ---------------------------------------------------------------------------
__global__ __launch_bounds__(1024) void finalize_dt_kernel(float* __restrict__ out, int out_size) {
    float m = g_blockmax[threadIdx.x];
    #pragma unroll
    for (int o = 16; o; o >>= 1) m = fmaxf(m, __shfl_xor_sync(0xffffffffu, m, o));
    __shared__ float sm[32];
    if ((threadIdx.x & 31) == 0) sm[threadIdx.x >> 5] = m;
    __syncthreads();
    if (threadIdx.x < 32) {
        m = sm[threadIdx.x];
        #pragma unroll
        for (int o = 16; o; o >>= 1) m = fmaxf(m, __shfl_xor_sync(0xffffffffu, m, o));
        if (threadIdx.x == 0) {
            const float dx = 1.0f / 126.0f;
            float dt_advect  = 0.05f * dx / m;                 // 0.5*CN_MAX*dx/uv_mag
            float a          = dx * dx;
            float dt_diffuse = 0.5f * (a * a) / (a + a);       // literal per reference
            float dt = fminf(dt_advect, dt_diffuse);
            g_dt = dt;
            if (out_size > NB * PLANE) out[NB * PLANE] = dt;
        }
    }
}

// ---------------------------------------------------------------------------
// Pass 3: fused advection + laplacian stencil. One 32x32 output tile per CTA.
// Clamped loads implement replicate padding; the advection stage is computed
// over the extended 34x34 tile so the laplacian's halo is exact.
// ---------------------------------------------------------------------------
__global__ __launch_bounds__(256) void stencil_kernel(const float* __restrict__ in,
                                                      float* __restrict__ out) {
    __shared__ float sT[TH][TH];   // T_prev, 2-halo
    __shared__ float sU[EX][EX];   // u, 1-halo
    __shared__ float sV[EX][EX];   // v, 1-halo
    __shared__ float sS[EX][EX];   // advection stage (T_new before diffusion)

    const int b   = blockIdx.z;
    const int bx0 = blockIdx.x * TS;
    const int by0 = blockIdx.y * TS;
    const float* __restrict__ U = in + (size_t)b * 4 * PLANE;
    const float* __restrict__ V = U + PLANE;
    const float* __restrict__ T = U + 2 * PLANE;
    const float* __restrict__ Q = U + 3 * PLANE;

    const int tid = threadIdx.y * 32 + threadIdx.x;

    // T tile with 2-halo (clamped = replicate pad)
    #pragma unroll
    for (int i = tid; i < TH * TH; i += 256) {
        int ly = i / TH, lx = i % TH;
        int gy = min(max(by0 + ly - 2, 0), NX - 1);
        int gx = min(max(bx0 + lx - 2, 0), NX - 1);
        sT[ly][lx] = T[gy * NX + gx];
    }
    // u,v tiles with 1-halo
    #pragma unroll
    for (int i = tid; i < EX * EX; i += 256) {
        int ly = i / EX, lx = i % EX;
        int gy = min(max(by0 + ly - 1, 0), NX - 1);
        int gx = min(max(bx0 + lx - 1, 0), NX - 1);
        sU[ly][lx] = U[gy * NX + gx];
        sV[ly][lx] = V[gy * NX + gx];
    }
    __syncthreads();

    const float dt     = g_dt;
    const float inv_dx = 126.0f;

    // Advection stage over extended tile. Clamp the CELL coordinate; neighbor
    // indexing +-1 in local coords then matches replicate-pad semantics exactly
    // because sT[r][s] = T[clamp(by0+r-2)][clamp(bx0+s-2)].
    #pragma unroll
    for (int i = tid; i < EX * EX; i += 256) {
        int ly = i / EX, lx = i % EX;
        int yc = min(max(by0 + ly - 1, 0), NX - 1) - by0 + 2;
        int xc = min(max(bx0 + lx - 1, 0), NX - 1) - bx0 + 2;
        float c  = sT[yc][xc];
        float dl = (c - sT[yc][xc - 1]) * inv_dx;
        float dr = (sT[yc][xc + 1] - c) * inv_dx;
        float dtp = (c - sT[yc - 1][xc]) * inv_dx;
        float dbt = (sT[yc + 1][xc] - c) * inv_dx;
        float u = sU[ly][lx], v = sV[ly][lx];
        float dTdx = (u > 0.f ? dl : 0.f) + (u < 0.f ? dr : 0.f);
        float dTdy = (v > 0.f ? dtp : 0.f) + (v < 0.f ? dbt : 0.f);
        sS[ly][lx] = c + dt * (-u * dTdx - v * dTdy);
    }
    __syncthreads();

    const float inv_dx2 = 126.0f * 126.0f;
    #pragma unroll
    for (int k = 0; k < 4; k++) {
        int oy = threadIdx.y + k * 8;
        int ox = threadIdx.x;
        int Yg = by0 + oy, Xg = bx0 + ox;
        float c11 = sS[oy + 1][ox + 1];
        float lap = 0.25f * inv_dx2 *
            (       sS[oy    ][ox] + 2.f * sS[oy    ][ox + 1] +       sS[oy    ][ox + 2]
            + 2.f * sS[oy + 1][ox] - 12.f * c11              + 2.f * sS[oy + 1][ox + 2]
            +       sS[oy + 2][ox] + 2.f * sS[oy + 2][ox + 1] +       sS[oy + 2][ox + 2]);
        out[(size_t)b * PLANE + Yg * NX + Xg] = c11 + dt * (lap + Q[Yg * NX + Xg]);
    }
}

extern "C" void kernel_launch(void* const* d_in, const int* in_sizes, int n_in,
                              void* d_out, int out_size) {
    const float* in = (const float*)d_in[0];
    float* out = (float*)d_out;

    reduce_max_kernel<<<RED_BLOCKS, 256>>>(in);
    finalize_dt_kernel<<<1, RED_BLOCKS>>>(out, out_size);

    dim3 grid(NX / TS, NX / TS, NB);
    dim3 block(32, 8);
    stencil_kernel<<<grid, block>>>(in, out);
}

// round 3
// speedup vs baseline: 1.1487x; 1.1487x over previous
#include <cuda_runtime.h>

#define NX 1024
#define PLANE (NX * NX)
#define NB 16
#define RH 64            // output rows per CTA chunk
#define RED_BLOCKS 1024

__device__ float g_blockmax[RED_BLOCKS];
__device__ float g_dt;

// ---------------------------------------------------------------------------
// Pass 1: max(|u|,|v|). Grid (64, NB). Each block: 8192 float4 of the
// contiguous u+v planes of one batch. 4 independent float4 loads per step.
// ---------------------------------------------------------------------------
__global__ __launch_bounds__(256) void reduce_max_kernel(const float* __restrict__ in) {
    const float4* __restrict__ p4 =
        reinterpret_cast<const float4*>(in + (size_t)blockIdx.y * 4 * PLANE);
    unsigned i0 = blockIdx.x * 8192u + threadIdx.x;   // 2*PLANE/4 = 524288 f4 / 64 blocks
    float m = 0.f;
    #pragma unroll
    for (int it = 0; it < 8; ++it) {
        float4 a = p4[i0 + it * 1024u];
        float4 b = p4[i0 + it * 1024u + 256u];
        float4 c = p4[i0 + it * 1024u + 512u];
        float4 d = p4[i0 + it * 1024u + 768u];
        float ma = fmaxf(fmaxf(fabsf(a.x), fabsf(a.y)), fmaxf(fabsf(a.z), fabsf(a.w)));
        float mb = fmaxf(fmaxf(fabsf(b.x), fabsf(b.y)), fmaxf(fabsf(b.z), fabsf(b.w)));
        float mc = fmaxf(fmaxf(fabsf(c.x), fabsf(c.y)), fmaxf(fabsf(c.z), fabsf(c.w)));
        float md = fmaxf(fmaxf(fabsf(d.x), fabsf(d.y)), fmaxf(fabsf(d.z), fabsf(d.w)));
        m = fmaxf(m, fmaxf(fmaxf(ma, mb), fmaxf(mc, md)));
    }
    #pragma unroll
    for (int o = 16; o; o >>= 1) m = fmaxf(m, __shfl_xor_sync(0xffffffffu, m, o));
    __shared__ float sm[8];
    if ((threadIdx.x & 31) == 0) sm[threadIdx.x >> 5] = m;
    __syncthreads();
    if (threadIdx.x < 32) {
        m = (threadIdx.x < 8) ? sm[threadIdx.x] : 0.f;
        #pragma unroll
        for (int o = 4; o; o >>= 1) m = fmaxf(m, __shfl_xor_sync(0xffffffffu, m, o));
        if (threadIdx.x == 0) g_blockmax[blockIdx.y * 64 + blockIdx.x] = m;
    }
}

// ---------------------------------------------------------------------------
// Pass 2: finalize dt.
// ---------------------------------------------------------------------------
__global__ __launch_bounds__(1024) void finalize_dt_kernel(float* __restrict__ out, int out_size) {
    float m = g_blockmax[threadIdx.x];
    #pragma unroll
    for (int o = 16; o; o >>= 1) m = fmaxf(m, __shfl_xor_sync(0xffffffffu, m, o));
    __shared__ float sm[32];
    if ((threadIdx.x & 31) == 0) sm[threadIdx.x >> 5] = m;
    __syncthreads();
    if (threadIdx.x < 32) {
        m = sm[threadIdx.x];
        #pragma unroll
        for (int o = 16; o; o >>= 1) m = fmaxf(m, __shfl_xor_sync(0xffffffffu, m, o));
        if (threadIdx.x == 0) {
            const float dx = 1.0f / 126.0f;
            float dt_advect  = 0.05f * dx / m;
            float a          = dx * dx;
            float dt_diffuse = 0.5f * (a * a) / (a + a);
            float dt = fminf(dt_advect, dt_diffuse);
            g_dt = dt;
            if (out_size > NB * PLANE) out[NB * PLANE] = dt;
        }
    }
}

// ---------------------------------------------------------------------------
// Pass 3: row-sweep fused stencil. 128-thread CTA owns a 128-wide strip,
// sweeps RH rows. T ring: 5 rows x 132 (2-col halo). A ring: 4 rows x 130
// (1-col halo). One __syncthreads per row; ring sizes make the single
// barrier separate every cross-iteration smem hazard.
// Ring slot for T row-counter r: (r - ry0 + 2) % 5  (holds T[clamp(r)]).
// Ring slot for A row-counter r: (r - ry0 + 1) % 4  (holds A at row clamp(r)).
// ---------------------------------------------------------------------------
__global__ __launch_bounds__(128) void stencil_sweep(const float* __restrict__ in,
                                                     float* __restrict__ out) {
    __shared__ float sT[5][132];
    __shared__ float sA[4][132];

    const int tx  = threadIdx.x;
    const int cx0 = blockIdx.x * 128;
    const int ry0 = blockIdx.y * RH;
    const float* __restrict__ U = in + (size_t)blockIdx.z * 4 * PLANE;
    const float* __restrict__ V = U + PLANE;
    const float* __restrict__ T = U + 2 * PLANE;
    const float* __restrict__ Q = U + 3 * PLANE;
    float* __restrict__ O = out + (size_t)blockIdx.z * PLANE;

    // column indices for this thread's T loads (clamped once, row-invariant)
    const int gxa = min(max(cx0 + tx - 2, 0), NX - 1);
    const int gxb = min(max(cx0 + 126 + tx, 0), NX - 1);   // for tx<4: cols 128..131

    // A-compute column mapping (row-invariant): la -> clamped global col + T index
    const int gc_a  = cx0 + tx - 1;                        // la = tx
    const int cc_a  = min(max(gc_a, 0), NX - 1);
    const int ts_a  = cc_a - cx0 + 2;                      // smem T col for clamped cell
    const int gc_b  = cx0 + 127 + tx;                      // la = 128+tx (tx<2)
    const int cc_b  = min(max(gc_b, 0), NX - 1);
    const int ts_b  = cc_b - cx0 + 2;

    #define LOAD_T(r) do {                                                   \
        int _s = ((r) - ry0 + 2) % 5;                                        \
        const float* _Tr = T + (size_t)min(max((r), 0), NX - 1) * NX;        \
        sT[_s][tx] = _Tr[gxa];                                               \
        if (tx < 4) sT[_s][128 + tx] = _Tr[gxb];                             \
    } while (0)

    #define COMPUTE_A(ar, dtv) do {                                          \
        int _sa  = ((ar) - ry0 + 1) & 3;                                     \
        int _rr  = min(max((ar), 0), NX - 1);                                \
        int _sm1 = (_rr - 1 - ry0 + 2) % 5;                                  \
        int _s0  = (_rr     - ry0 + 2) % 5;                                  \
        int _sp1 = (_rr + 1 - ry0 + 2) % 5;                                  \
        const float* _Ur = U + (size_t)_rr * NX;                             \
        const float* _Vr = V + (size_t)_rr * NX;                             \
        {   float c  = sT[_s0][ts_a];                                        \
            float dl = (c - sT[_s0][ts_a - 1]) * 126.f;                      \
            float dr = (sT[_s0][ts_a + 1] - c) * 126.f;                      \
            float dtp= (c - sT[_sm1][ts_a]) * 126.f;                         \
            float dbt= (sT[_sp1][ts_a] - c) * 126.f;                         \
            float u = _Ur[cc_a], v = _Vr[cc_a];                              \
            float gx = (u > 0.f ? dl : 0.f) + (u < 0.f ? dr : 0.f);          \
            float gy = (v > 0.f ? dtp : 0.f) + (v < 0.f ? dbt : 0.f);        \
            sA[_sa][tx] = c + (dtv) * (-u * gx - v * gy);                    \
        }                                                                    \
        if (tx < 2) {                                                        \
            float c  = sT[_s0][ts_b];                                        \
            float dl = (c - sT[_s0][ts_b - 1]) * 126.f;                      \
            float dr = (sT[_s0][ts_b + 1] - c) * 126.f;                      \
            float dtp= (c - sT[_sm1][ts_b]) * 126.f;                         \
            float dbt= (sT[_sp1][ts_b] - c) * 126.f;                         \
            float u = _Ur[cc_b], v = _Vr[cc_b];                              \
            float gx = (u > 0.f ? dl : 0.f) + (u < 0.f ? dr : 0.f);          \
            float gy = (v > 0.f ? dtp : 0.f) + (v < 0.f ? dbt : 0.f);        \
            sA[_sa][128 + tx] = c + (dtv) * (-u * gx - v * gy);              \
        }                                                                    \
    } while (0)

    // Prologue: fill 5 T rows (counters ry0-2 .. ry0+2), compute A rows ry0-1, ry0.
    LOAD_T(ry0 - 2); LOAD_T(ry0 - 1); LOAD_T(ry0); LOAD_T(ry0 + 1); LOAD_T(ry0 + 2);
    __syncthreads();
    const float dt = g_dt;
    COMPUTE_A(ry0 - 1, dt);
    COMPUTE_A(ry0,     dt);
    __syncthreads();

    const float k = 0.25f * 126.f * 126.f;
    for (int y = ry0; y < ry0 + RH; ++y) {
        COMPUTE_A(y + 1, dt);        // needs T[y..y+2] (in ring)
        LOAD_T(y + 3);               // for next iteration's A (distinct slot)
        __syncthreads();             // publishes A[y+1] and T[y+3]

        int a0 = (y - 1 - ry0 + 1) & 3;
        int a1 = (y     - ry0 + 1) & 3;
        int a2 = (y + 1 - ry0 + 1) & 3;
        int la = tx + 1;
        float c11 = sA[a1][la];
        float lap = k * (        sA[a0][la - 1] + 2.f * sA[a0][la] +       sA[a0][la + 1]
                         + 2.f * sA[a1][la - 1] - 12.f * c11       + 2.f * sA[a1][la + 1]
                         +       sA[a2][la - 1] + 2.f * sA[a2][la] +       sA[a2][la + 1]);
        size_t gi = (size_t)y * NX + cx0 + tx;
        O[gi] = c11 + dt * (lap + Q[gi]);
    }
    #undef LOAD_T
    #undef COMPUTE_A
}

extern "C" void kernel_launch(void* const* d_in, const int* in_sizes, int n_in,
                              void* d_out, int out_size) {
    const float* in = (const float*)d_in[0];
    float* out = (float*)d_out;

    reduce_max_kernel<<<dim3(64, NB), 256>>>(in);
    finalize_dt_kernel<<<1, RED_BLOCKS>>>(out, out_size);

    dim3 grid(NX / 128, NX / RH, NB);
    stencil_sweep<<<grid, 128>>>(in, out);
}

// round 4
// speedup vs baseline: 1.7272x; 1.5036x over previous
#include <cuda_runtime.h>

#define NX 1024
#define PLANE (NX * NX)
#define NB 16
#define RH 32            // rows swept per CTA
#define RED_BLOCKS 1024

__device__ float g_blockmax[RED_BLOCKS];
__device__ float g_dt;

// ---------------------------------------------------------------------------
// Pass 1: max(|u|,|v|). Grid (64, NB), 256 thr. 8 independent float4 loads
// per unrolled step, split accumulators.
// ---------------------------------------------------------------------------
__global__ __launch_bounds__(256) void reduce_max_kernel(const float* __restrict__ in) {
    const float4* __restrict__ p4 =
        reinterpret_cast<const float4*>(in + (size_t)blockIdx.y * 4 * PLANE);
    unsigned i0 = blockIdx.x * 8192u + threadIdx.x;
    float m0 = 0.f, m1 = 0.f;
    #pragma unroll
    for (int it = 0; it < 4; ++it) {
        unsigned base = i0 + it * 2048u;
        float4 a = p4[base         ];
        float4 b = p4[base +  256u ];
        float4 c = p4[base +  512u ];
        float4 d = p4[base +  768u ];
        float4 e = p4[base + 1024u ];
        float4 f = p4[base + 1280u ];
        float4 g = p4[base + 1536u ];
        float4 h = p4[base + 1792u ];
        m0 = fmaxf(m0, fmaxf(fmaxf(fabsf(a.x), fabsf(a.y)), fmaxf(fabsf(a.z), fabsf(a.w))));
        m1 = fmaxf(m1, fmaxf(fmaxf(fabsf(b.x), fabsf(b.y)), fmaxf(fabsf(b.z), fabsf(b.w))));
        m0 = fmaxf(m0, fmaxf(fmaxf(fabsf(c.x), fabsf(c.y)), fmaxf(fabsf(c.z), fabsf(c.w))));
        m1 = fmaxf(m1, fmaxf(fmaxf(fabsf(d.x), fabsf(d.y)), fmaxf(fabsf(d.z), fabsf(d.w))));
        m0 = fmaxf(m0, fmaxf(fmaxf(fabsf(e.x), fabsf(e.y)), fmaxf(fabsf(e.z), fabsf(e.w))));
        m1 = fmaxf(m1, fmaxf(fmaxf(fabsf(f.x), fabsf(f.y)), fmaxf(fabsf(f.z), fabsf(f.w))));
        m0 = fmaxf(m0, fmaxf(fmaxf(fabsf(g.x), fabsf(g.y)), fmaxf(fabsf(g.z), fabsf(g.w))));
        m1 = fmaxf(m1, fmaxf(fmaxf(fabsf(h.x), fabsf(h.y)), fmaxf(fabsf(h.z), fabsf(h.w))));
    }
    float m = fmaxf(m0, m1);
    #pragma unroll
    for (int o = 16; o; o >>= 1) m = fmaxf(m, __shfl_xor_sync(0xffffffffu, m, o));
    __shared__ float sm[8];
    if ((threadIdx.x & 31) == 0) sm[threadIdx.x >> 5] = m;
    __syncthreads();
    if (threadIdx.x < 32) {
        m = (threadIdx.x < 8) ? sm[threadIdx.x] : 0.f;
        #pragma unroll
        for (int o = 4; o; o >>= 1) m = fmaxf(m, __shfl_xor_sync(0xffffffffu, m, o));
        if (threadIdx.x == 0) g_blockmax[blockIdx.y * 64 + blockIdx.x] = m;
    }
}

// ---------------------------------------------------------------------------
// Pass 2: finalize dt.
// ---------------------------------------------------------------------------
__global__ __launch_bounds__(1024) void finalize_dt_kernel(float* __restrict__ out, int out_size) {
    float m = g_blockmax[threadIdx.x];
    #pragma unroll
    for (int o = 16; o; o >>= 1) m = fmaxf(m, __shfl_xor_sync(0xffffffffu, m, o));
    __shared__ float sm[32];
    if ((threadIdx.x & 31) == 0) sm[threadIdx.x >> 5] = m;
    __syncthreads();
    if (threadIdx.x < 32) {
        m = sm[threadIdx.x];
        #pragma unroll
        for (int o = 16; o; o >>= 1) m = fmaxf(m, __shfl_xor_sync(0xffffffffu, m, o));
        if (threadIdx.x == 0) {
            const float dx = 1.0f / 126.0f;
            float dt_advect  = 0.05f * dx / m;
            float a          = dx * dx;
            float dt_diffuse = 0.5f * (a * a) / (a + a);
            float dt = fminf(dt_advect, dt_diffuse);
            g_dt = dt;
            if (out_size > NB * PLANE) out[NB * PLANE] = dt;
        }
    }
}

// ---------------------------------------------------------------------------
// Pass 3: whole-row sweep. 256 thr x float4 = full 1024-col row per CTA.
// T ring: 5 rows, A ring: 4 rows. All global loads pipelined 1 iter ahead.
// TSLOT(r) holds T[clamp(r)]; ASLOT(r) holds advection stage at row clamp(r).
// ---------------------------------------------------------------------------
__device__ __forceinline__ float adv_pt(float c, float l, float r, float t, float b,
                                        float u, float v, float dt) {
    float dl  = (c - l) * 126.f, dr  = (r - c) * 126.f;
    float dtp = (c - t) * 126.f, dbt = (b - c) * 126.f;
    float gx = (u > 0.f ? dl : 0.f) + (u < 0.f ? dr : 0.f);
    float gy = (v > 0.f ? dtp : 0.f) + (v < 0.f ? dbt : 0.f);
    return c + dt * (-u * gx - v * gy);
}

__global__ __launch_bounds__(256, 4) void stencil_sweep(const float* __restrict__ in,
                                                        float* __restrict__ out) {
    __shared__ float sT[5][NX];
    __shared__ float sA[4][NX];

    const int tx  = threadIdx.x;
    const int c0  = tx * 4;
    const int lc  = max(c0 - 1, 0);
    const int rc  = min(c0 + 4, NX - 1);
    const int ry0 = blockIdx.y * RH;
    const float* __restrict__ U = in + (size_t)blockIdx.z * 4 * PLANE;
    const float* __restrict__ V = U + PLANE;
    const float* __restrict__ T = U + 2 * PLANE;
    const float* __restrict__ Q = U + 3 * PLANE;
    float* __restrict__ O = out + (size_t)blockIdx.z * PLANE;

    #define TSLOT(r) (((r) - ry0 + 2) % 5)
    #define ASLOT(r) (((r) - ry0 + 1) & 3)
    #define F4G(p)   (*reinterpret_cast<const float4*>(p))
    #define F4S(p)   (*reinterpret_cast<float4*>(p))

    const float dt = g_dt;

    // ---- prologue: fill T ring (counters ry0-2 .. ry0+2) ----
    #pragma unroll
    for (int k = -2; k <= 2; ++k) {
        int rr = min(max(ry0 + k, 0), NX - 1);
        F4S(&sT[TSLOT(ry0 + k)][c0]) = F4G(T + (size_t)rr * NX + c0);
    }
    // pipeline registers
    float4 Tn = F4G(T + (size_t)min(ry0 + 3, NX - 1) * NX + c0);   // counter ry0+3
    int run = min(max(ry0 + 1, 0), NX - 1);
    float4 Un = F4G(U + (size_t)run * NX + c0);                    // for A(ry0+1)
    float4 Vn = F4G(V + (size_t)run * NX + c0);
    float4 Qn = F4G(Q + (size_t)ry0 * NX + c0);                    // for lap row ry0
    // u,v for prologue A rows
    int rm1 = max(ry0 - 1, 0);
    float4 Um = F4G(U + (size_t)rm1 * NX + c0);
    float4 Vm = F4G(V + (size_t)rm1 * NX + c0);
    float4 U0 = F4G(U + (size_t)ry0 * NX + c0);
    float4 V0 = F4G(V + (size_t)ry0 * NX + c0);
    __syncthreads();

    // compute A(ry0-1), A(ry0)
    #pragma unroll
    for (int pk = 0; pk < 2; ++pk) {
        int ar = ry0 - 1 + pk;
        int rr = min(max(ar, 0), NX - 1);
        int sm1 = TSLOT(rr - 1), s0 = TSLOT(rr), sp1 = TSLOT(rr + 1);
        float4 c  = F4G(&sT[s0][c0]);
        float  lf = sT[s0][lc], rt = sT[s0][rc];
        float4 up = F4G(&sT[sm1][c0]);
        float4 dn = F4G(&sT[sp1][c0]);
        float4 uu = pk ? U0 : Um;
        float4 vv = pk ? V0 : Vm;
        float4 a;
        a.x = adv_pt(c.x, lf,  c.y, up.x, dn.x, uu.x, vv.x, dt);
        a.y = adv_pt(c.y, c.x, c.z, up.y, dn.y, uu.y, vv.y, dt);
        a.z = adv_pt(c.z, c.y, c.w, up.z, dn.z, uu.z, vv.z, dt);
        a.w = adv_pt(c.w, c.z, rt,  up.w, dn.w, uu.w, vv.w, dt);
        F4S(&sA[ASLOT(ar)][c0]) = a;
    }
    __syncthreads();

    const float kq = 0.25f * 126.f * 126.f;
    for (int y = ry0; y < ry0 + RH; ++y) {
        // 1. issue next-iteration loads
        float4 t2 = F4G(T + (size_t)min(y + 4, NX - 1) * NX + c0);
        int rn = min(y + 2, NX - 1);
        float4 u2 = F4G(U + (size_t)rn * NX + c0);
        float4 v2 = F4G(V + (size_t)rn * NX + c0);
        float4 q2 = F4G(Q + (size_t)min(y + 1, NX - 1) * NX + c0);

        // 2. publish T counter y+3 (loaded last iter)
        F4S(&sT[TSLOT(y + 3)][c0]) = Tn;

        // 3. compute A(y+1) from T rows y..y+2 (already published) + Un/Vn
        {
            int ar = y + 1;
            int rr = min(max(ar, 0), NX - 1);
            int sm1 = TSLOT(rr - 1), s0 = TSLOT(rr), sp1 = TSLOT(rr + 1);
            float4 c  = F4G(&sT[s0][c0]);
            float  lf = sT[s0][lc], rt = sT[s0][rc];
            float4 up = F4G(&sT[sm1][c0]);
            float4 dn = F4G(&sT[sp1][c0]);
            float4 a;
            a.x = adv_pt(c.x, lf,  c.y, up.x, dn.x, Un.x, Vn.x, dt);
            a.y = adv_pt(c.y, c.x, c.z, up.y, dn.y, Un.y, Vn.y, dt);
            a.z = adv_pt(c.z, c.y, c.w, up.z, dn.z, Un.z, Vn.z, dt);
            a.w = adv_pt(c.w, c.z, rt,  up.w, dn.w, Un.w, Vn.w, dt);
            F4S(&sA[ASLOT(ar)][c0]) = a;
        }
        __syncthreads();

        // 4. laplacian at row y (sA rows y-1..y+1), add Qn, store
        {
            int a0 = ASLOT(y - 1), a1 = ASLOT(y), a2 = ASLOT(y + 1);
            float4 m0 = F4G(&sA[a0][c0]); float l0 = sA[a0][lc], r0 = sA[a0][rc];
            float4 m1 = F4G(&sA[a1][c0]); float l1 = sA[a1][lc], r1 = sA[a1][rc];
            float4 m2 = F4G(&sA[a2][c0]); float l2 = sA[a2][lc], r2 = sA[a2][rc];
            float4 res;
            {
                float lap = kq * ((l0 + 2.f * m0.x + m0.y)
                                + (2.f * l1 - 12.f * m1.x + 2.f * m1.y)
                                + (l2 + 2.f * m2.x + m2.y));
                res.x = m1.x + dt * (lap + Qn.x);
            }
            {
                float lap = kq * ((m0.x + 2.f * m0.y + m0.z)
                                + (2.f * m1.x - 12.f * m1.y + 2.f * m1.z)
                                + (m2.x + 2.f * m2.y + m2.z));
                res.y = m1.y + dt * (lap + Qn.y);
            }
            {
                float lap = kq * ((m0.y + 2.f * m0.z + m0.w)
                                + (2.f * m1.y - 12.f * m1.z + 2.f * m1.w)
                                + (m2.y + 2.f * m2.z + m2.w));
                res.z = m1.z + dt * (lap + Qn.z);
            }
            {
                float lap = kq * ((m0.z + 2.f * m0.w + r0)
                                + (2.f * m1.z - 12.f * m1.w + 2.f * r1)
                                + (m2.z + 2.f * m2.w + r2));
                res.w = m1.w + dt * (lap + Qn.w);
            }
            F4S(O + (size_t)y * NX + c0) = res;
        }

        // 5. rotate pipeline
        Tn = t2; Un = u2; Vn = v2; Qn = q2;
    }
    #undef TSLOT
    #undef ASLOT
    #undef F4G
    #undef F4S
}

extern "C" void kernel_launch(void* const* d_in, const int* in_sizes, int n_in,
                              void* d_out, int out_size) {
    const float* in = (const float*)d_in[0];
    float* out = (float*)d_out;

    reduce_max_kernel<<<dim3(64, NB), 256>>>(in);
    finalize_dt_kernel<<<1, RED_BLOCKS>>>(out, out_size);

    dim3 grid(1, NX / RH, NB);
    stencil_sweep<<<grid, 256>>>(in, out);
}